// round 13
// baseline (speedup 1.0000x reference)
#include <cuda_runtime.h>
#include <math.h>

#define D 128

// ---------------------------------------------------------------------------
// Scratch (device globals — zero-init at load; kernels restore the all-zero
// invariant every call, so NO runtime memsets are needed).
// ---------------------------------------------------------------------------
#define MAXROWS 716800          // >= NE+NF+NA+NF+NE = 700000
__device__ float    g_agg[(size_t)MAXROWS * D];   // segment sums (self-zeroing)
__device__ float    g_cnt[MAXROWS];               // counts (self-zeroing)
__device__ unsigned g_B[5 * 2 * D * D];           // tf32 bits: [t][wl|wr][n][k]

// ---------------------------------------------------------------------------
// prep: convert all 5 wl / wr matrices to tf32 bits. Layout [t][side][n*128+k]
// ---------------------------------------------------------------------------
struct PrepParams { const float* wl[5]; const float* wr[5]; };

__global__ void prep_kernel(PrepParams p) {
    int i = blockIdx.x * blockDim.x + threadIdx.x;      // 0 .. 163839
    int t = i >> 15;
    int r = i & 32767;
    int side = r >> 14;
    int idx = r & 16383;
    float v = (side ? p.wr[t] : p.wl[t])[idx];
    unsigned u;
    asm("cvt.rna.tf32.f32 %0, %1;" : "=r"(u) : "f"(v));
    g_B[i] = u;
}

// ---------------------------------------------------------------------------
// Scatter (per segment, up to 2 edge types): TWO edges per warp (MLP 2).
// ---------------------------------------------------------------------------
struct ScatParams {
    const float* xs[2];
    const int*   si[2];
    const int*   di[2];
    size_t aggOff[2];
    int    cntOff[2];
    long long ePrefix[3];   // cumulative EDGE counts over this segment's types
};

__global__ void scatter_kernel(ScatParams p) {
    long long gt = (long long)blockIdx.x * blockDim.x + threadIdx.x;
    long long w = gt >> 5;
    int c = (int)(gt & 31);
    long long E = p.ePrefix[2];
    long long e0 = w * 2;
    if (e0 >= E) return;
    long long e1 = e0 + 1;
    bool has1 = (e1 < E);

    int t0 = (e0 >= p.ePrefix[1]) ? 1 : 0;
    int i0 = (int)(e0 - p.ePrefix[t0]);
    int s0 = p.si[t0][i0];
    int d0 = p.di[t0][i0];

    int t1 = t0, s1 = 0, d1 = 0;
    if (has1) {
        t1 = (e1 >= p.ePrefix[1]) ? 1 : 0;
        int i1 = (int)(e1 - p.ePrefix[t1]);
        s1 = p.si[t1][i1];
        d1 = p.di[t1][i1];
    }

    // issue both gathers back-to-back (independent chains)
    float4 v0 = ((const float4*)(p.xs[t0] + (size_t)s0 * D))[c];
    float4 v1 = make_float4(0.f, 0.f, 0.f, 0.f);
    if (has1) v1 = ((const float4*)(p.xs[t1] + (size_t)s1 * D))[c];

    float* dst0 = g_agg + p.aggOff[t0] + (size_t)d0 * D + c * 4;
    asm volatile("red.global.add.v4.f32 [%0], {%1,%2,%3,%4};"
                 :: "l"(dst0), "f"(v0.x), "f"(v0.y), "f"(v0.z), "f"(v0.w)
                 : "memory");
    if (c == 0) atomicAdd(g_cnt + p.cntOff[t0] + d0, 1.0f);

    if (has1) {
        float* dst1 = g_agg + p.aggOff[t1] + (size_t)d1 * D + c * 4;
        asm volatile("red.global.add.v4.f32 [%0], {%1,%2,%3,%4};"
                     :: "l"(dst1), "f"(v1.x), "f"(v1.y), "f"(v1.z), "f"(v1.w)
                     : "memory");
        if (c == 0) atomicAdd(g_cnt + p.cntOff[t1] + d1, 1.0f);
    }
}

// ---------------------------------------------------------------------------
// Per-segment GEMM, tf32 mma.sync.m16n8k8, cp.async 3-stage pipeline, BK=32.
// One block owns 128 rows and runs 1-2 passes: pass 0 plain store, pass 1
// load-add-store (L2-hot, same rows). Per pass: agg tiles (wr) first ->
// scale by 1/cnt -> xd tiles (wl); then +bias, row L2-norm.
// agg/cnt rezeroed in place (restores invariant; lines L2-hot post-scatter).
// ---------------------------------------------------------------------------
__device__ __forceinline__ void mma_tf32(float* c, const unsigned* a,
                                         unsigned b0, unsigned b1) {
    asm volatile(
        "mma.sync.aligned.m16n8k8.row.col.f32.tf32.tf32.f32 "
        "{%0,%1,%2,%3}, {%4,%5,%6,%7}, {%8,%9}, {%0,%1,%2,%3};"
        : "+f"(c[0]), "+f"(c[1]), "+f"(c[2]), "+f"(c[3])
        : "r"(a[0]), "r"(a[1]), "r"(a[2]), "r"(a[3]), "r"(b0), "r"(b1));
}

struct GemmParams {
    const float* xd;
    float*       out;
    int          nd;
    int          npass;
    const float* bias[2];
    size_t       aggOff[2];
    int          cntOff[2];
    int          tIdx[2];
};

#define TILEW (128 * 36)     // words per As or Bs buffer (stride 36 -> 144B)
#define STAGES 3

__global__ __launch_bounds__(256, 2) void gemm_kernel(GemmParams p) {
    extern __shared__ unsigned sm[];   // STAGES * [As | Bs]
    typedef unsigned Row36[36];

    int rowBase = blockIdx.x * 128;
    int n_dst = p.nd;
    const float* xd = p.xd;
    float* outp = p.out;
    int npass = p.npass;

    __shared__ float rowsum[2][128];
    __shared__ float invc_s[128];

    int tid = threadIdx.x;
    int wid = tid >> 5, lane = tid & 31;
    int warpM = wid & 3, warpN = wid >> 2;
    int lq = lane & 3;
    int lr = lane >> 2;

    unsigned smBase = (unsigned)__cvta_generic_to_shared(sm);

    for (int pass = 0; pass < npass; pass++) {
        float* agg = g_agg + p.aggOff[pass];
        float* cnt = g_cnt + p.cntOff[pass];
        const unsigned* Bl = g_B + (size_t)p.tIdx[pass] * 32768;  // wl
        const unsigned* Br = Bl + 16384;                           // wr

        // counts: read once, rezero in place
        if (tid < 128) {
            int gr = rowBase + tid;
            float cc = 1.0f;
            if (gr < n_dst) { cc = cnt[gr]; cnt[gr] = 0.0f; }
            invc_s[tid] = 1.0f / fmaxf(cc, 1.0f);
        }

        float acc[2][8][4];
#pragma unroll
        for (int mt = 0; mt < 2; mt++)
#pragma unroll
            for (int nt = 0; nt < 8; nt++)
#pragma unroll
                for (int r = 0; r < 4; r++) acc[mt][nt][r] = 0.f;

        // tile kt: kt<4 -> agg rows with wr; kt>=4 -> xd rows with wl
        auto issueTile = [&](int kt, int buf) {
            bool isAgg = (kt < 4);
            int kLocal = (kt & 3) * 32;
            const float* srcA = isAgg ? (const float*)agg : xd;
            const unsigned* Bp = isAgg ? Br : Bl;
            unsigned aBase = smBase + (unsigned)(buf * 2 * TILEW) * 4u;
            unsigned bBase = aBase + (unsigned)TILEW * 4u;
#pragma unroll
            for (int it = 0; it < 4; it++) {
                int f = it * 256 + tid;       // 0..1023 16B chunks
                int r = f >> 3;
                int c4 = f & 7;
                int gr = rowBase + r;
                unsigned ad = aBase + (unsigned)(r * 36 + c4 * 4) * 4u;
                const float* asrc = srcA + (size_t)gr * D + kLocal + c4 * 4;
                int sz = (gr < n_dst) ? 16 : 0;     // OOB -> zero-fill
                asm volatile("cp.async.cg.shared.global [%0], [%1], 16, %2;"
                             :: "r"(ad), "l"(asrc), "r"(sz));
                unsigned bd = bBase + (unsigned)(r * 36 + c4 * 4) * 4u;
                const unsigned* bsrc = Bp + (size_t)r * D + kLocal + c4 * 4;
                asm volatile("cp.async.cg.shared.global [%0], [%1], 16;"
                             :: "r"(bd), "l"(bsrc));
            }
            asm volatile("cp.async.commit_group;" ::: "memory");
        };

        issueTile(0, 0);
        issueTile(1, 1);

        for (int kt = 0; kt < 8; kt++) {
            int buf = kt % STAGES;
            if (kt < 7)
                asm volatile("cp.async.wait_group 1;" ::: "memory");
            else
                asm volatile("cp.async.wait_group 0;" ::: "memory");
            __syncthreads();      // tile kt visible; mma on buf's prior tile done
            if (kt < 6) issueTile(kt + 2, (kt + 2) % STAGES);

            Row36* As = (Row36*)(sm + buf * 2 * TILEW);
            Row36* Bs = As + 128;
#pragma unroll
            for (int k8 = 0; k8 < 4; k8++) {
                int kq = k8 * 8 + lq;
                unsigned a[2][4];
#pragma unroll
                for (int mt = 0; mt < 2; mt++) {
                    int r0 = warpM * 32 + mt * 16 + lr;
                    a[mt][0] = As[r0][kq];
                    a[mt][1] = As[r0 + 8][kq];
                    a[mt][2] = As[r0][kq + 4];
                    a[mt][3] = As[r0 + 8][kq + 4];
                }
#pragma unroll
                for (int nt = 0; nt < 8; nt++) {
                    int n0 = warpN * 64 + nt * 8 + lr;
                    unsigned b0 = Bs[n0][kq];
                    unsigned b1 = Bs[n0][kq + 4];
                    mma_tf32(acc[0][nt], a[0], b0, b1);
                    mma_tf32(acc[1][nt], a[1], b0, b1);
                }
            }

            if (kt == 3) {
                // finished agg@wr^T: scale by 1/cnt; xd@wl^T adds on top
#pragma unroll
                for (int mt = 0; mt < 2; mt++) {
                    int r0 = warpM * 32 + mt * 16 + lr;
                    float s0 = invc_s[r0];
                    float s1 = invc_s[r0 + 8];
#pragma unroll
                    for (int nt = 0; nt < 8; nt++) {
                        acc[mt][nt][0] *= s0; acc[mt][nt][1] *= s0;
                        acc[mt][nt][2] *= s1; acc[mt][nt][3] *= s1;
                    }
                }
            }
        }

        // ---- rezero this pass's agg rows: 128 x 128 = 4096 float4 ----
#pragma unroll
        for (int it = 0; it < 16; it++) {
            int f = it * 256 + tid;
            int r = f >> 5;
            int c = f & 31;
            int gr = rowBase + r;
            if (gr < n_dst)
                *(float4*)(agg + (size_t)gr * D + c * 4) =
                    make_float4(0.f, 0.f, 0.f, 0.f);
        }

        // ---- epilogue: bias, row L2-norm, store ----
        const float* bias = p.bias[pass];
        float biasv[16];
#pragma unroll
        for (int nt = 0; nt < 8; nt++) {
            float2 bb = *(const float2*)(bias + warpN * 64 + nt * 8 + 2 * lq);
            biasv[2 * nt] = bb.x;
            biasv[2 * nt + 1] = bb.y;
        }

        float ps[2][2] = {{0.f, 0.f}, {0.f, 0.f}};
#pragma unroll
        for (int mt = 0; mt < 2; mt++)
#pragma unroll
            for (int nt = 0; nt < 8; nt++) {
                acc[mt][nt][0] += biasv[2 * nt];
                acc[mt][nt][1] += biasv[2 * nt + 1];
                acc[mt][nt][2] += biasv[2 * nt];
                acc[mt][nt][3] += biasv[2 * nt + 1];
                ps[mt][0] += acc[mt][nt][0] * acc[mt][nt][0]
                           + acc[mt][nt][1] * acc[mt][nt][1];
                ps[mt][1] += acc[mt][nt][2] * acc[mt][nt][2]
                           + acc[mt][nt][3] * acc[mt][nt][3];
            }
#pragma unroll
        for (int mt = 0; mt < 2; mt++)
#pragma unroll
            for (int h = 0; h < 2; h++) {
                float v = ps[mt][h];
                v += __shfl_xor_sync(0xffffffffu, v, 1);
                v += __shfl_xor_sync(0xffffffffu, v, 2);
                if (lq == 0)
                    rowsum[warpN][warpM * 32 + mt * 16 + h * 8 + lr] = v;
            }
        __syncthreads();

#pragma unroll
        for (int mt = 0; mt < 2; mt++)
#pragma unroll
            for (int h = 0; h < 2; h++) {
                int rloc = warpM * 32 + mt * 16 + h * 8 + lr;
                int gr = rowBase + rloc;
                if (gr >= n_dst) continue;
                float ss = rowsum[0][rloc] + rowsum[1][rloc];
                float inv = 1.f / fmaxf(sqrtf(ss), 1e-12f);
#pragma unroll
                for (int nt = 0; nt < 8; nt++) {
                    float vx = acc[mt][nt][h * 2 + 0] * inv;
                    float vy = acc[mt][nt][h * 2 + 1] * inv;
                    float* pp = outp + (size_t)gr * D + warpN * 64 + nt * 8 + 2 * lq;
                    if (pass == 0) {
                        *(float2*)pp = make_float2(vx, vy);
                    } else {
                        float2 old = *(const float2*)pp;   // L2-hot (own rows)
                        *(float2*)pp = make_float2(old.x + vx, old.y + vy);
                    }
                }
            }
    }
}

// ---------------------------------------------------------------------------
// Host orchestration — single stream, segment-interleaved:
//   prep -> [scatter(seg) -> gemm(seg)] for seg in {entity, fact, article}.
// Keeps each segment's agg (<=102MB) L2-resident between scatter and gemm.
// ---------------------------------------------------------------------------
extern "C" void kernel_launch(void* const* d_in, const int* in_sizes, int n_in,
                              void* d_out, int out_size) {
    const float* xa = (const float*)d_in[0];
    const float* xe = (const float*)d_in[1];
    const float* xf = (const float*)d_in[2];
    int NA = in_sizes[0] / D;
    int NE = in_sizes[1] / D;
    int NF = in_sizes[2] / D;

    float* out = (float*)d_out;
    float* out_a = out;
    float* out_e = out + (size_t)NA * D;
    float* out_f = out + (size_t)(NA + NE) * D;

    // EDGE_TYPES: (a->e), (a->f), (e->a), (e->f), (f->e)
    const float* xs_t[5] = {xa, xa, xe, xe, xf};
    int nd_t[5]          = {NE, NF, NA, NF, NE};

    PrepParams pp;
    size_t aggOffA[5];
    int cntOffA[5];
    int rowCum = 0;
    for (int t = 0; t < 5; t++) {
        pp.wl[t] = (const float*)d_in[13 + 3 * t];
        pp.wr[t] = (const float*)d_in[15 + 3 * t];
        aggOffA[t] = (size_t)rowCum * D;
        cntOffA[t] = rowCum;
        rowCum += nd_t[t];
    }

    // Segments: entity {0,4}, fact {1,3}, article {2}
    struct Seg { const float* xd; float* out; int nd; int npass; int tt[2]; };
    Seg segs[3] = {
        { xe, out_e, NE, 2, {0, 4} },
        { xf, out_f, NF, 2, {1, 3} },
        { xa, out_a, NA, 1, {2, 2} },
    };

    int smemBytes = STAGES * 2 * TILEW * 4;      // 110592
    cudaFuncSetAttribute(gemm_kernel,
                         cudaFuncAttributeMaxDynamicSharedMemorySize, smemBytes);

    prep_kernel<<<(5 * 2 * D * D) / 256, 256>>>(pp);

    for (int s = 0; s < 3; s++) {
        Seg& sg = segs[s];
        int ntypes = (sg.npass == 2) ? 2 : 1;

        ScatParams sp;
        long long cum = 0;
        sp.ePrefix[0] = 0;
        for (int i = 0; i < 2; i++) {
            int t = sg.tt[(i < ntypes) ? i : ntypes - 1];
            sp.xs[i] = xs_t[t];
            sp.si[i] = (const int*)d_in[3 + 2 * t];
            sp.di[i] = (const int*)d_in[4 + 2 * t];
            sp.aggOff[i] = aggOffA[t];
            sp.cntOff[i] = cntOffA[t];
            if (i < ntypes) cum += in_sizes[3 + 2 * t];
            sp.ePrefix[i + 1] = cum;
        }
        long long nw = (cum + 1) / 2;            // two edges per warp
        long long thr = nw * 32;
        scatter_kernel<<<(int)((thr + 255) / 256), 256>>>(sp);

        GemmParams gp;
        gp.xd = sg.xd; gp.out = sg.out; gp.nd = sg.nd; gp.npass = sg.npass;
        for (int q = 0; q < 2; q++) {
            int t = sg.tt[q];
            gp.aggOff[q] = aggOffA[t];
            gp.cntOff[q] = cntOffA[t];
            gp.bias[q] = (const float*)d_in[14 + 3 * t];
            gp.tIdx[q] = t;
        }
        gemm_kernel<<<(sg.nd + 127) / 128, 256, smemBytes>>>(gp);
    }
}

// round 14
// speedup vs baseline: 1.6415x; 1.6415x over previous
#include <cuda_runtime.h>
#include <cuda_fp16.h>
#include <math.h>

#define D 128

// ---------------------------------------------------------------------------
// Scratch (device globals — zero-init at load; kernels restore the all-zero
// invariant every call, so NO runtime memsets are needed).
// ---------------------------------------------------------------------------
#define MAXROWS 716800          // >= NE+NF+NA+NF+NE = 700000
__device__ __half   g_aggH[(size_t)MAXROWS * D];  // fp16 segment sums (self-zeroing)
__device__ float    g_cnt[MAXROWS];               // counts (self-zeroing)
__device__ unsigned g_Bwl[5 * D * D];             // tf32 bits: [t][n][k] (wl)
__device__ __half   g_BwrH[5 * D * D];            // fp16:      [t][n][k] (wr)

// ---------------------------------------------------------------------------
// prep: wl -> tf32 bits, wr -> fp16. Layout [t][n*128+k].
// ---------------------------------------------------------------------------
struct PrepParams { const float* wl[5]; const float* wr[5]; };

__global__ void prep_kernel(PrepParams p) {
    int i = blockIdx.x * blockDim.x + threadIdx.x;      // 0 .. 163839
    int t = i >> 15;
    int r = i & 32767;
    int side = r >> 14;
    int idx = r & 16383;
    if (side == 0) {
        float v = p.wl[t][idx];
        unsigned u;
        asm("cvt.rna.tf32.f32 %0, %1;" : "=r"(u) : "f"(v));
        g_Bwl[t * 16384 + idx] = u;
    } else {
        g_BwrH[t * 16384 + idx] = __float2half_rn(p.wr[t][idx]);
    }
}

// ---------------------------------------------------------------------------
// Mega-scatter: TWO edges per warp (MLP 2), fp16x2 vector reductions.
// Lane c handles halfs [4c..4c+3] of the 128-half agg row (8 bytes).
// ---------------------------------------------------------------------------
struct ScatParams {
    const float* xs[5];
    const int*   si[5];
    const int*   di[5];
    size_t aggOff[5];       // in halfs
    int    cntOff[5];
    long long ePrefix[6];   // cumulative EDGE counts
};

__device__ __forceinline__ void red_f16x2v2(__half* dst, float4 v) {
    __half2 h0 = __floats2half2_rn(v.x, v.y);
    __half2 h1 = __floats2half2_rn(v.z, v.w);
    unsigned u0 = *(unsigned*)&h0;
    unsigned u1 = *(unsigned*)&h1;
    asm volatile("red.global.add.noftz.v2.f16x2 [%0], {%1,%2};"
                 :: "l"(dst), "r"(u0), "r"(u1) : "memory");
}

__global__ void scatter_kernel(ScatParams p) {
    long long gt = (long long)blockIdx.x * blockDim.x + threadIdx.x;
    long long w = gt >> 5;
    int c = (int)(gt & 31);
    long long E = p.ePrefix[5];
    long long e0 = w * 2;
    if (e0 >= E) return;
    long long e1 = e0 + 1;
    bool has1 = (e1 < E);

    int t0 = 0;
    while (e0 >= p.ePrefix[t0 + 1]) t0++;
    int i0 = (int)(e0 - p.ePrefix[t0]);
    int s0 = p.si[t0][i0];
    int d0 = p.di[t0][i0];

    int t1 = t0, s1 = 0, d1 = 0;
    if (has1) {
        while (e1 >= p.ePrefix[t1 + 1]) t1++;
        int i1 = (int)(e1 - p.ePrefix[t1]);
        s1 = p.si[t1][i1];
        d1 = p.di[t1][i1];
    }

    // issue both gathers back-to-back (independent chains)
    float4 v0 = ((const float4*)(p.xs[t0] + (size_t)s0 * D))[c];
    float4 v1 = make_float4(0.f, 0.f, 0.f, 0.f);
    if (has1) v1 = ((const float4*)(p.xs[t1] + (size_t)s1 * D))[c];

    red_f16x2v2(g_aggH + p.aggOff[t0] + (size_t)d0 * D + c * 4, v0);
    if (c == 0) atomicAdd(g_cnt + p.cntOff[t0] + d0, 1.0f);

    if (has1) {
        red_f16x2v2(g_aggH + p.aggOff[t1] + (size_t)d1 * D + c * 4, v1);
        if (c == 0) atomicAdd(g_cnt + p.cntOff[t1] + d1, 1.0f);
    }
}

// ---------------------------------------------------------------------------
// FUSED Mega-GEMM, cp.async 3-stage pipeline, 6 tiles per pass:
//   tiles 0-1: agg fp16 (BK=64 halfs) with wr -> mma.m16n8k16.f16 (f32 acc)
//   tiles 2-5: xd fp32 (BK=32)       with wl -> mma.m16n8k8.tf32
// Tiles are byte-identical (16KB A + 16KB B, stride-36 words) so the
// pipeline/fragment addressing is shared; only the mma opcode differs.
// After tile 1: scale acc by 1/cnt (mean). Pass 0 plain store, pass 1
// load-add-store (L2-hot). agg/cnt rezeroed in place per pass.
// ---------------------------------------------------------------------------
__device__ __forceinline__ void mma_tf32(float* c, const unsigned* a,
                                         unsigned b0, unsigned b1) {
    asm volatile(
        "mma.sync.aligned.m16n8k8.row.col.f32.tf32.tf32.f32 "
        "{%0,%1,%2,%3}, {%4,%5,%6,%7}, {%8,%9}, {%0,%1,%2,%3};"
        : "+f"(c[0]), "+f"(c[1]), "+f"(c[2]), "+f"(c[3])
        : "r"(a[0]), "r"(a[1]), "r"(a[2]), "r"(a[3]), "r"(b0), "r"(b1));
}

__device__ __forceinline__ void mma_f16(float* c, const unsigned* a,
                                        unsigned b0, unsigned b1) {
    asm volatile(
        "mma.sync.aligned.m16n8k16.row.col.f32.f16.f16.f32 "
        "{%0,%1,%2,%3}, {%4,%5,%6,%7}, {%8,%9}, {%0,%1,%2,%3};"
        : "+f"(c[0]), "+f"(c[1]), "+f"(c[2]), "+f"(c[3])
        : "r"(a[0]), "r"(a[1]), "r"(a[2]), "r"(a[3]), "r"(b0), "r"(b1));
}

struct GemmParams {
    const float* xd[3];
    float*       out[3];
    int          nd[3];
    int          npass[3];
    int          blkPrefix[4];
    const float* bias[3][2];
    size_t       aggOff[3][2];   // in halfs
    int          cntOff[3][2];
    int          tIdx[3][2];
};

#define TILEW (128 * 36)     // words per As or Bs buffer (stride 36 -> 144B)
#define STAGES 3

__global__ __launch_bounds__(256, 2) void gemm_kernel(GemmParams p) {
    extern __shared__ unsigned sm[];   // STAGES * [As | Bs]
    typedef unsigned Row36[36];

    int b = blockIdx.x;
    int seg = (b >= p.blkPrefix[1]) + (b >= p.blkPrefix[2]);
    int rowBase = (b - p.blkPrefix[seg]) * 128;
    int n_dst = p.nd[seg];
    const float* xd = p.xd[seg];
    float* outp = p.out[seg];
    int npass = p.npass[seg];

    __shared__ float rowsum[2][128];
    __shared__ float invc_s[128];

    int tid = threadIdx.x;
    int wid = tid >> 5, lane = tid & 31;
    int warpM = wid & 3, warpN = wid >> 2;
    int lq = lane & 3;
    int lr = lane >> 2;

    unsigned smBase = (unsigned)__cvta_generic_to_shared(sm);

    for (int pass = 0; pass < npass; pass++) {
        __half* aggH = g_aggH + p.aggOff[seg][pass];
        float*  cnt  = g_cnt + p.cntOff[seg][pass];
        const unsigned* Bwl = g_Bwl + (size_t)p.tIdx[seg][pass] * 16384;
        const __half*   BwrH = g_BwrH + (size_t)p.tIdx[seg][pass] * 16384;

        // counts: read once, rezero in place
        if (tid < 128) {
            int gr = rowBase + tid;
            float cc = 1.0f;
            if (gr < n_dst) { cc = cnt[gr]; cnt[gr] = 0.0f; }
            invc_s[tid] = 1.0f / fmaxf(cc, 1.0f);
        }

        float acc[2][8][4];
#pragma unroll
        for (int mt = 0; mt < 2; mt++)
#pragma unroll
            for (int nt = 0; nt < 8; nt++)
#pragma unroll
                for (int r = 0; r < 4; r++) acc[mt][nt][r] = 0.f;

        // tile kt: kt<2 -> agg fp16 (BK=64 halfs); kt>=2 -> xd fp32 (BK=32)
        auto issueTile = [&](int kt, int buf) {
            unsigned aBase = smBase + (unsigned)(buf * 2 * TILEW) * 4u;
            unsigned bBase = aBase + (unsigned)TILEW * 4u;
            bool isAgg = (kt < 2);
            const char* aSrc;
            const char* bSrc;
            size_t aRowB, bRowB; int kB;
            if (isAgg) {
                aSrc = (const char*)aggH;  bSrc = (const char*)BwrH;
                aRowB = 256; bRowB = 256; kB = kt * 128;
            } else {
                aSrc = (const char*)xd;    bSrc = (const char*)Bwl;
                aRowB = 512; bRowB = 512; kB = (kt - 2) * 128;
            }
#pragma unroll
            for (int it = 0; it < 4; it++) {
                int f = it * 256 + tid;       // 0..1023 16B chunks
                int r = f >> 3;
                int c4 = f & 7;
                int gr = rowBase + r;
                unsigned ad = aBase + (unsigned)(r * 36 + c4 * 4) * 4u;
                const char* asrc = aSrc + (size_t)gr * aRowB + kB + c4 * 16;
                int sz = (gr < n_dst) ? 16 : 0;     // OOB -> zero-fill
                asm volatile("cp.async.cg.shared.global [%0], [%1], 16, %2;"
                             :: "r"(ad), "l"(asrc), "r"(sz));
                unsigned bd = bBase + (unsigned)(r * 36 + c4 * 4) * 4u;
                const char* bsrc = bSrc + (size_t)r * bRowB + kB + c4 * 16;
                asm volatile("cp.async.cg.shared.global [%0], [%1], 16;"
                             :: "r"(bd), "l"(bsrc));
            }
            asm volatile("cp.async.commit_group;" ::: "memory");
        };

        issueTile(0, 0);
        issueTile(1, 1);

        for (int kt = 0; kt < 6; kt++) {
            int buf = kt % STAGES;
            if (kt < 5)
                asm volatile("cp.async.wait_group 1;" ::: "memory");
            else
                asm volatile("cp.async.wait_group 0;" ::: "memory");
            __syncthreads();      // tile kt visible; mma on buf's prior tile done
            if (kt < 4) issueTile(kt + 2, (kt + 2) % STAGES);

            Row36* As = (Row36*)(sm + buf * 2 * TILEW);
            Row36* Bs = As + 128;
            bool isAgg = (kt < 2);
#pragma unroll
            for (int g = 0; g < 4; g++) {
                int kq = g * 8 + lq;
                unsigned a[2][4];
#pragma unroll
                for (int mt = 0; mt < 2; mt++) {
                    int r0 = warpM * 32 + mt * 16 + lr;
                    a[mt][0] = As[r0][kq];
                    a[mt][1] = As[r0 + 8][kq];
                    a[mt][2] = As[r0][kq + 4];
                    a[mt][3] = As[r0 + 8][kq + 4];
                }
#pragma unroll
                for (int nt = 0; nt < 8; nt++) {
                    int n0 = warpN * 64 + nt * 8 + lr;
                    unsigned b0 = Bs[n0][kq];
                    unsigned b1 = Bs[n0][kq + 4];
                    if (isAgg) {
                        mma_f16(acc[0][nt], a[0], b0, b1);
                        mma_f16(acc[1][nt], a[1], b0, b1);
                    } else {
                        mma_tf32(acc[0][nt], a[0], b0, b1);
                        mma_tf32(acc[1][nt], a[1], b0, b1);
                    }
                }
            }

            if (kt == 1) {
                // finished aggSum@wr^T: scale by 1/cnt; xd@wl^T adds on top
#pragma unroll
                for (int mt = 0; mt < 2; mt++) {
                    int r0 = warpM * 32 + mt * 16 + lr;
                    float s0 = invc_s[r0];
                    float s1 = invc_s[r0 + 8];
#pragma unroll
                    for (int nt = 0; nt < 8; nt++) {
                        acc[mt][nt][0] *= s0; acc[mt][nt][1] *= s0;
                        acc[mt][nt][2] *= s1; acc[mt][nt][3] *= s1;
                    }
                }
            }
        }

        // ---- rezero this pass's agg rows: 128 rows x 256B = 2048 uint4 ----
#pragma unroll
        for (int it = 0; it < 8; it++) {
            int f = it * 256 + tid;            // 0..2047
            int r = f >> 4;                    // 0..127
            int c = f & 15;                    // 16B chunk within row
            int gr = rowBase + r;
            if (gr < n_dst)
                *(uint4*)((char*)(aggH + (size_t)gr * D) + c * 16) =
                    make_uint4(0, 0, 0, 0);
        }

        // ---- epilogue: bias, row L2-norm, store ----
        const float* bias = p.bias[seg][pass];
        float biasv[16];
#pragma unroll
        for (int nt = 0; nt < 8; nt++) {
            float2 bb = *(const float2*)(bias + warpN * 64 + nt * 8 + 2 * lq);
            biasv[2 * nt] = bb.x;
            biasv[2 * nt + 1] = bb.y;
        }

        float ps[2][2] = {{0.f, 0.f}, {0.f, 0.f}};
#pragma unroll
        for (int mt = 0; mt < 2; mt++)
#pragma unroll
            for (int nt = 0; nt < 8; nt++) {
                acc[mt][nt][0] += biasv[2 * nt];
                acc[mt][nt][1] += biasv[2 * nt + 1];
                acc[mt][nt][2] += biasv[2 * nt];
                acc[mt][nt][3] += biasv[2 * nt + 1];
                ps[mt][0] += acc[mt][nt][0] * acc[mt][nt][0]
                           + acc[mt][nt][1] * acc[mt][nt][1];
                ps[mt][1] += acc[mt][nt][2] * acc[mt][nt][2]
                           + acc[mt][nt][3] * acc[mt][nt][3];
            }
#pragma unroll
        for (int mt = 0; mt < 2; mt++)
#pragma unroll
            for (int h = 0; h < 2; h++) {
                float v = ps[mt][h];
                v += __shfl_xor_sync(0xffffffffu, v, 1);
                v += __shfl_xor_sync(0xffffffffu, v, 2);
                if (lq == 0)
                    rowsum[warpN][warpM * 32 + mt * 16 + h * 8 + lr] = v;
            }
        __syncthreads();

#pragma unroll
        for (int mt = 0; mt < 2; mt++)
#pragma unroll
            for (int h = 0; h < 2; h++) {
                int rloc = warpM * 32 + mt * 16 + h * 8 + lr;
                int gr = rowBase + rloc;
                if (gr >= n_dst) continue;
                float ss = rowsum[0][rloc] + rowsum[1][rloc];
                float inv = 1.f / fmaxf(sqrtf(ss), 1e-12f);
#pragma unroll
                for (int nt = 0; nt < 8; nt++) {
                    float vx = acc[mt][nt][h * 2 + 0] * inv;
                    float vy = acc[mt][nt][h * 2 + 1] * inv;
                    float* pp = outp + (size_t)gr * D + warpN * 64 + nt * 8 + 2 * lq;
                    if (pass == 0) {
                        *(float2*)pp = make_float2(vx, vy);
                    } else {
                        float2 old = *(const float2*)pp;   // L2-hot (own rows)
                        *(float2*)pp = make_float2(old.x + vx, old.y + vy);
                    }
                }
            }
    }
}

// ---------------------------------------------------------------------------
// Host orchestration — single stream, 3 launches: prep, mega-scatter, fused
// gemm (R12 shape; R13's segment-split scatter reverted).
// ---------------------------------------------------------------------------
extern "C" void kernel_launch(void* const* d_in, const int* in_sizes, int n_in,
                              void* d_out, int out_size) {
    const float* xa = (const float*)d_in[0];
    const float* xe = (const float*)d_in[1];
    const float* xf = (const float*)d_in[2];
    int NA = in_sizes[0] / D;
    int NE = in_sizes[1] / D;
    int NF = in_sizes[2] / D;

    float* out = (float*)d_out;
    float* out_a = out;
    float* out_e = out + (size_t)NA * D;
    float* out_f = out + (size_t)(NA + NE) * D;

    // EDGE_TYPES: (a->e), (a->f), (e->a), (e->f), (f->e)
    const float* xs_t[5] = {xa, xa, xe, xe, xf};
    int nd_t[5]          = {NE, NF, NA, NF, NE};

    PrepParams pp;
    ScatParams sp;

    size_t aggOffA[5];
    int cntOffA[5];
    int rowCum = 0;
    long long eCum = 0;
    sp.ePrefix[0] = 0;
    for (int t = 0; t < 5; t++) {
        pp.wl[t] = (const float*)d_in[13 + 3 * t];
        pp.wr[t] = (const float*)d_in[15 + 3 * t];
        sp.xs[t] = xs_t[t];
        sp.si[t] = (const int*)d_in[3 + 2 * t];
        sp.di[t] = (const int*)d_in[4 + 2 * t];
        sp.aggOff[t] = (size_t)rowCum * D;
        sp.cntOff[t] = rowCum;
        aggOffA[t] = (size_t)rowCum * D;
        cntOffA[t] = rowCum;
        rowCum += nd_t[t];
        eCum += in_sizes[3 + 2 * t];
        sp.ePrefix[t + 1] = eCum;
    }

    // Fused GEMM segments: entity (2-pass), fact (2-pass), article (1-pass).
    GemmParams gp;
    gp.xd[0] = xe;  gp.out[0] = out_e;  gp.nd[0] = NE;  gp.npass[0] = 2;
    gp.tIdx[0][0] = 0; gp.tIdx[0][1] = 4;
    gp.xd[1] = xf;  gp.out[1] = out_f;  gp.nd[1] = NF;  gp.npass[1] = 2;
    gp.tIdx[1][0] = 1; gp.tIdx[1][1] = 3;
    gp.xd[2] = xa;  gp.out[2] = out_a;  gp.nd[2] = NA;  gp.npass[2] = 1;
    gp.tIdx[2][0] = 2; gp.tIdx[2][1] = 2;
    for (int s = 0; s < 3; s++)
        for (int q = 0; q < 2; q++) {
            int t = gp.tIdx[s][q];
            gp.aggOff[s][q] = aggOffA[t];
            gp.cntOff[s][q] = cntOffA[t];
            gp.bias[s][q] = (const float*)d_in[14 + 3 * t];
        }
    int bE = (NE + 127) / 128;
    int bF = (NF + 127) / 128;
    int bA = (NA + 127) / 128;
    gp.blkPrefix[0] = 0;
    gp.blkPrefix[1] = bE;
    gp.blkPrefix[2] = bE + bF;
    gp.blkPrefix[3] = bE + bF + bA;

    int smemBytes = STAGES * 2 * TILEW * 4;      // 110592
    cudaFuncSetAttribute(gemm_kernel,
                         cudaFuncAttributeMaxDynamicSharedMemorySize, smemBytes);

    prep_kernel<<<(5 * 2 * D * D) / 256, 256>>>(pp);

    long long nw = (eCum + 1) / 2;               // two edges per warp
    long long thr = nw * 32;
    int sblk = (int)((thr + 255) / 256);
    scatter_kernel<<<sblk, 256>>>(sp);

    gemm_kernel<<<gp.blkPrefix[3], 256, smemBytes>>>(gp);
}

// round 15
// speedup vs baseline: 1.8835x; 1.1474x over previous
#include <cuda_runtime.h>
#include <cuda_fp16.h>
#include <math.h>

#define D 128

// ---------------------------------------------------------------------------
// Scratch (device globals — zero-init at load; kernels restore the all-zero
// invariant every call; g_xH / g_Bh are fully rewritten every call).
// ---------------------------------------------------------------------------
#define MAXROWS 716800          // >= NE+NF+NA+NF+NE = 700000
#define MAXSRC  409600          // >= NA+NE+NF = 400000
__device__ __half   g_aggH[(size_t)MAXROWS * D];  // fp16 segment sums (self-zeroing)
__device__ float    g_cnt[MAXROWS];               // counts (self-zeroing)
__device__ __half   g_xH[(size_t)MAXSRC * D];     // fp16 feature tables [xa;xe;xf]
__device__ __half   g_Bh[5 * 2 * D * D];          // fp16 weights: [t][wl|wr][n][k]

// ---------------------------------------------------------------------------
// prep: convert all 5 wl / wr matrices to fp16. Layout [t][side][n*128+k]
// ---------------------------------------------------------------------------
struct PrepParams { const float* wl[5]; const float* wr[5]; };

__global__ void prep_kernel(PrepParams p) {
    int i = blockIdx.x * blockDim.x + threadIdx.x;      // 0 .. 163839
    int t = i >> 15;
    int r = i & 32767;
    int side = r >> 14;
    int idx = r & 16383;
    float v = (side ? p.wr[t] : p.wl[t])[idx];
    g_Bh[i] = __float2half_rn(v);
}

// ---------------------------------------------------------------------------
// cvt: stream-convert the three feature tables fp32 -> fp16 into g_xH.
// Each thread: 8 floats (2x float4 read, 1x uint4 write).
// ---------------------------------------------------------------------------
struct CvtParams { const float* src[3]; long long prefix[4]; };  // prefix in floats

__global__ void cvt_kernel(CvtParams p) {
    long long i = (long long)blockIdx.x * blockDim.x + threadIdx.x;
    long long f = i * 8;
    if (f >= p.prefix[3]) return;
    int t = 0;
    while (f >= p.prefix[t + 1]) t++;
    long long loc = f - p.prefix[t];
    const float4* s = (const float4*)(p.src[t] + loc);
    float4 a = s[0], b = s[1];
    __half2 h0 = __floats2half2_rn(a.x, a.y);
    __half2 h1 = __floats2half2_rn(a.z, a.w);
    __half2 h2 = __floats2half2_rn(b.x, b.y);
    __half2 h3 = __floats2half2_rn(b.z, b.w);
    uint4 o;
    o.x = *(unsigned*)&h0; o.y = *(unsigned*)&h1;
    o.z = *(unsigned*)&h2; o.w = *(unsigned*)&h3;
    *(uint4*)(g_xH + p.prefix[t] + loc) = o;
}

// ---------------------------------------------------------------------------
// Mega-scatter: TWO edges per warp (MLP 2). Gathers fp16 rows (8B/lane,
// L2-resident tables), RED fp16x2 pairs — no conversion in the loop.
// ---------------------------------------------------------------------------
struct ScatParams {
    size_t srcOff[5];       // source-table base in g_xH (halfs)
    const int* si[5];
    const int* di[5];
    size_t aggOff[5];       // in halfs
    int    cntOff[5];
    long long ePrefix[6];   // cumulative EDGE counts
};

__global__ void scatter_kernel(ScatParams p) {
    long long gt = (long long)blockIdx.x * blockDim.x + threadIdx.x;
    long long w = gt >> 5;
    int c = (int)(gt & 31);
    long long E = p.ePrefix[5];
    long long e0 = w * 2;
    if (e0 >= E) return;
    long long e1 = e0 + 1;
    bool has1 = (e1 < E);

    int t0 = 0;
    while (e0 >= p.ePrefix[t0 + 1]) t0++;
    int i0 = (int)(e0 - p.ePrefix[t0]);
    int s0 = p.si[t0][i0];
    int d0 = p.di[t0][i0];

    int t1 = t0, s1 = 0, d1 = 0;
    if (has1) {
        while (e1 >= p.ePrefix[t1 + 1]) t1++;
        int i1 = (int)(e1 - p.ePrefix[t1]);
        s1 = p.si[t1][i1];
        d1 = p.di[t1][i1];
    }

    // both gathers issued back-to-back (independent chains)
    uint2 v0 = ((const uint2*)(g_xH + p.srcOff[t0] + (size_t)s0 * D))[c];
    uint2 v1 = make_uint2(0, 0);
    if (has1) v1 = ((const uint2*)(g_xH + p.srcOff[t1] + (size_t)s1 * D))[c];

    __half* dst0 = g_aggH + p.aggOff[t0] + (size_t)d0 * D + c * 4;
    asm volatile("red.global.add.noftz.v2.f16x2 [%0], {%1,%2};"
                 :: "l"(dst0), "r"(v0.x), "r"(v0.y) : "memory");
    if (c == 0) atomicAdd(g_cnt + p.cntOff[t0] + d0, 1.0f);

    if (has1) {
        __half* dst1 = g_aggH + p.aggOff[t1] + (size_t)d1 * D + c * 4;
        asm volatile("red.global.add.noftz.v2.f16x2 [%0], {%1,%2};"
                     :: "l"(dst1), "r"(v1.x), "r"(v1.y) : "memory");
        if (c == 0) atomicAdd(g_cnt + p.cntOff[t1] + d1, 1.0f);
    }
}

// ---------------------------------------------------------------------------
// FUSED Mega-GEMM, all-fp16 operands, f32 accum, cp.async 3-stage pipeline.
// 4 tiles per pass (BK=64 halfs): tiles 0-1 agg@wr, then scale by 1/cnt;
// tiles 2-3 xd@wl. Pass 0 plain store, pass 1 load-add-store (L2-hot).
// agg/cnt rezeroed in place per pass. Epilogue: +bias, row L2-norm.
// ---------------------------------------------------------------------------
__device__ __forceinline__ void mma_f16(float* c, const unsigned* a,
                                        unsigned b0, unsigned b1) {
    asm volatile(
        "mma.sync.aligned.m16n8k16.row.col.f32.f16.f16.f32 "
        "{%0,%1,%2,%3}, {%4,%5,%6,%7}, {%8,%9}, {%0,%1,%2,%3};"
        : "+f"(c[0]), "+f"(c[1]), "+f"(c[2]), "+f"(c[3])
        : "r"(a[0]), "r"(a[1]), "r"(a[2]), "r"(a[3]), "r"(b0), "r"(b1));
}

struct GemmParams {
    size_t       xdOff[3];       // dst-node features base in g_xH (halfs)
    float*       out[3];
    int          nd[3];
    int          npass[3];
    int          blkPrefix[4];
    const float* bias[3][2];
    size_t       aggOff[3][2];   // in halfs
    int          cntOff[3][2];
    int          tIdx[3][2];
};

#define TILEW (128 * 36)     // words per As or Bs buffer (stride 36 -> 144B)
#define STAGES 3

__global__ __launch_bounds__(256, 2) void gemm_kernel(GemmParams p) {
    extern __shared__ unsigned sm[];   // STAGES * [As | Bs]
    typedef unsigned Row36[36];

    int b = blockIdx.x;
    int seg = (b >= p.blkPrefix[1]) + (b >= p.blkPrefix[2]);
    int rowBase = (b - p.blkPrefix[seg]) * 128;
    int n_dst = p.nd[seg];
    const __half* xdH = g_xH + p.xdOff[seg];
    float* outp = p.out[seg];
    int npass = p.npass[seg];

    __shared__ float rowsum[2][128];
    __shared__ float invc_s[128];

    int tid = threadIdx.x;
    int wid = tid >> 5, lane = tid & 31;
    int warpM = wid & 3, warpN = wid >> 2;
    int lq = lane & 3;
    int lr = lane >> 2;

    unsigned smBase = (unsigned)__cvta_generic_to_shared(sm);

    for (int pass = 0; pass < npass; pass++) {
        __half* aggH = g_aggH + p.aggOff[seg][pass];
        float*  cnt  = g_cnt + p.cntOff[seg][pass];
        const __half* wlH = g_Bh + (size_t)p.tIdx[seg][pass] * 32768;
        const __half* wrH = wlH + 16384;

        // counts: read once, rezero in place
        if (tid < 128) {
            int gr = rowBase + tid;
            float cc = 1.0f;
            if (gr < n_dst) { cc = cnt[gr]; cnt[gr] = 0.0f; }
            invc_s[tid] = 1.0f / fmaxf(cc, 1.0f);
        }

        float acc[2][8][4];
#pragma unroll
        for (int mt = 0; mt < 2; mt++)
#pragma unroll
            for (int nt = 0; nt < 8; nt++)
#pragma unroll
                for (int r = 0; r < 4; r++) acc[mt][nt][r] = 0.f;

        // tile kt: kt<2 -> agg rows with wr; kt>=2 -> xd rows with wl.
        // All tiles: 128 rows x 64 halfs (128B per row chunk).
        auto issueTile = [&](int kt, int buf) {
            unsigned aBase = smBase + (unsigned)(buf * 2 * TILEW) * 4u;
            unsigned bBase = aBase + (unsigned)TILEW * 4u;
            bool isAgg = (kt < 2);
            const char* aSrc = isAgg ? (const char*)aggH : (const char*)xdH;
            const char* bSrc = isAgg ? (const char*)wrH : (const char*)wlH;
            int kB = (kt & 1) * 128;
#pragma unroll
            for (int it = 0; it < 4; it++) {
                int f = it * 256 + tid;       // 0..1023 16B chunks
                int r = f >> 3;
                int c4 = f & 7;
                int gr = rowBase + r;
                unsigned ad = aBase + (unsigned)(r * 36 + c4 * 4) * 4u;
                const char* asrc = aSrc + (size_t)gr * 256 + kB + c4 * 16;
                int sz = (gr < n_dst) ? 16 : 0;     // OOB -> zero-fill
                asm volatile("cp.async.cg.shared.global [%0], [%1], 16, %2;"
                             :: "r"(ad), "l"(asrc), "r"(sz));
                unsigned bd = bBase + (unsigned)(r * 36 + c4 * 4) * 4u;
                const char* bsrc = bSrc + (size_t)r * 256 + kB + c4 * 16;
                asm volatile("cp.async.cg.shared.global [%0], [%1], 16;"
                             :: "r"(bd), "l"(bsrc));
            }
            asm volatile("cp.async.commit_group;" ::: "memory");
        };

        issueTile(0, 0);
        issueTile(1, 1);

        for (int kt = 0; kt < 4; kt++) {
            int buf = kt % STAGES;
            if (kt < 3)
                asm volatile("cp.async.wait_group 1;" ::: "memory");
            else
                asm volatile("cp.async.wait_group 0;" ::: "memory");
            __syncthreads();      // tile kt visible; mma on buf's prior tile done
            if (kt < 2) issueTile(kt + 2, (kt + 2) % STAGES);

            Row36* As = (Row36*)(sm + buf * 2 * TILEW);
            Row36* Bs = As + 128;
#pragma unroll
            for (int g = 0; g < 4; g++) {
                int kq = g * 8 + lq;
                unsigned a[2][4];
#pragma unroll
                for (int mt = 0; mt < 2; mt++) {
                    int r0 = warpM * 32 + mt * 16 + lr;
                    a[mt][0] = As[r0][kq];
                    a[mt][1] = As[r0 + 8][kq];
                    a[mt][2] = As[r0][kq + 4];
                    a[mt][3] = As[r0 + 8][kq + 4];
                }
#pragma unroll
                for (int nt = 0; nt < 8; nt++) {
                    int n0 = warpN * 64 + nt * 8 + lr;
                    unsigned b0 = Bs[n0][kq];
                    unsigned b1 = Bs[n0][kq + 4];
                    mma_f16(acc[0][nt], a[0], b0, b1);
                    mma_f16(acc[1][nt], a[1], b0, b1);
                }
            }

            if (kt == 1) {
                // finished aggSum@wr^T: scale by 1/cnt; xd@wl^T adds on top
#pragma unroll
                for (int mt = 0; mt < 2; mt++) {
                    int r0 = warpM * 32 + mt * 16 + lr;
                    float s0 = invc_s[r0];
                    float s1 = invc_s[r0 + 8];
#pragma unroll
                    for (int nt = 0; nt < 8; nt++) {
                        acc[mt][nt][0] *= s0; acc[mt][nt][1] *= s0;
                        acc[mt][nt][2] *= s1; acc[mt][nt][3] *= s1;
                    }
                }
            }
        }

        // ---- rezero this pass's agg rows: 128 rows x 256B = 2048 uint4 ----
#pragma unroll
        for (int it = 0; it < 8; it++) {
            int f = it * 256 + tid;            // 0..2047
            int r = f >> 4;                    // 0..127
            int c = f & 15;                    // 16B chunk within row
            int gr = rowBase + r;
            if (gr < n_dst)
                *(uint4*)((char*)(aggH + (size_t)gr * D) + c * 16) =
                    make_uint4(0, 0, 0, 0);
        }

        // ---- epilogue: bias, row L2-norm, store ----
        const float* bias = p.bias[seg][pass];
        float biasv[16];
#pragma unroll
        for (int nt = 0; nt < 8; nt++) {
            float2 bb = *(const float2*)(bias + warpN * 64 + nt * 8 + 2 * lq);
            biasv[2 * nt] = bb.x;
            biasv[2 * nt + 1] = bb.y;
        }

        float ps[2][2] = {{0.f, 0.f}, {0.f, 0.f}};
#pragma unroll
        for (int mt = 0; mt < 2; mt++)
#pragma unroll
            for (int nt = 0; nt < 8; nt++) {
                acc[mt][nt][0] += biasv[2 * nt];
                acc[mt][nt][1] += biasv[2 * nt + 1];
                acc[mt][nt][2] += biasv[2 * nt];
                acc[mt][nt][3] += biasv[2 * nt + 1];
                ps[mt][0] += acc[mt][nt][0] * acc[mt][nt][0]
                           + acc[mt][nt][1] * acc[mt][nt][1];
                ps[mt][1] += acc[mt][nt][2] * acc[mt][nt][2]
                           + acc[mt][nt][3] * acc[mt][nt][3];
            }
#pragma unroll
        for (int mt = 0; mt < 2; mt++)
#pragma unroll
            for (int h = 0; h < 2; h++) {
                float v = ps[mt][h];
                v += __shfl_xor_sync(0xffffffffu, v, 1);
                v += __shfl_xor_sync(0xffffffffu, v, 2);
                if (lq == 0)
                    rowsum[warpN][warpM * 32 + mt * 16 + h * 8 + lr] = v;
            }
        __syncthreads();

#pragma unroll
        for (int mt = 0; mt < 2; mt++)
#pragma unroll
            for (int h = 0; h < 2; h++) {
                int rloc = warpM * 32 + mt * 16 + h * 8 + lr;
                int gr = rowBase + rloc;
                if (gr >= n_dst) continue;
                float ss = rowsum[0][rloc] + rowsum[1][rloc];
                float inv = 1.f / fmaxf(sqrtf(ss), 1e-12f);
#pragma unroll
                for (int nt = 0; nt < 8; nt++) {
                    float vx = acc[mt][nt][h * 2 + 0] * inv;
                    float vy = acc[mt][nt][h * 2 + 1] * inv;
                    float* pp = outp + (size_t)gr * D + warpN * 64 + nt * 8 + 2 * lq;
                    if (pass == 0) {
                        *(float2*)pp = make_float2(vx, vy);
                    } else {
                        float2 old = *(const float2*)pp;   // L2-hot (own rows)
                        *(float2*)pp = make_float2(old.x + vx, old.y + vy);
                    }
                }
            }
    }
}

// ---------------------------------------------------------------------------
// Host orchestration — single stream, 4 launches: prep, cvt, mega-scatter,
// fused gemm.
// ---------------------------------------------------------------------------
extern "C" void kernel_launch(void* const* d_in, const int* in_sizes, int n_in,
                              void* d_out, int out_size) {
    const float* xa = (const float*)d_in[0];
    const float* xe = (const float*)d_in[1];
    const float* xf = (const float*)d_in[2];
    int NA = in_sizes[0] / D;
    int NE = in_sizes[1] / D;
    int NF = in_sizes[2] / D;

    float* out = (float*)d_out;
    float* out_a = out;
    float* out_e = out + (size_t)NA * D;
    float* out_f = out + (size_t)(NA + NE) * D;

    // g_xH layout: [xa ; xe ; xf] (halfs)
    size_t offA = 0;
    size_t offE = (size_t)NA * D;
    size_t offF = (size_t)(NA + NE) * D;

    // EDGE_TYPES: (a->e), (a->f), (e->a), (e->f), (f->e)
    size_t srcOff_t[5] = {offA, offA, offE, offE, offF};
    int nd_t[5]        = {NE, NF, NA, NF, NE};

    PrepParams pp;
    ScatParams sp;
    CvtParams cp;

    cp.src[0] = xa; cp.src[1] = xe; cp.src[2] = xf;
    cp.prefix[0] = 0;
    cp.prefix[1] = (long long)NA * D;
    cp.prefix[2] = (long long)(NA + NE) * D;
    cp.prefix[3] = (long long)(NA + NE + NF) * D;

    size_t aggOffA[5];
    int cntOffA[5];
    int rowCum = 0;
    long long eCum = 0;
    sp.ePrefix[0] = 0;
    for (int t = 0; t < 5; t++) {
        pp.wl[t] = (const float*)d_in[13 + 3 * t];
        pp.wr[t] = (const float*)d_in[15 + 3 * t];
        sp.srcOff[t] = srcOff_t[t];
        sp.si[t] = (const int*)d_in[3 + 2 * t];
        sp.di[t] = (const int*)d_in[4 + 2 * t];
        sp.aggOff[t] = (size_t)rowCum * D;
        sp.cntOff[t] = rowCum;
        aggOffA[t] = (size_t)rowCum * D;
        cntOffA[t] = rowCum;
        rowCum += nd_t[t];
        eCum += in_sizes[3 + 2 * t];
        sp.ePrefix[t + 1] = eCum;
    }

    // Fused GEMM segments: entity (2-pass), fact (2-pass), article (1-pass).
    GemmParams gp;
    gp.xdOff[0] = offE;  gp.out[0] = out_e;  gp.nd[0] = NE;  gp.npass[0] = 2;
    gp.tIdx[0][0] = 0; gp.tIdx[0][1] = 4;
    gp.xdOff[1] = offF;  gp.out[1] = out_f;  gp.nd[1] = NF;  gp.npass[1] = 2;
    gp.tIdx[1][0] = 1; gp.tIdx[1][1] = 3;
    gp.xdOff[2] = offA;  gp.out[2] = out_a;  gp.nd[2] = NA;  gp.npass[2] = 1;
    gp.tIdx[2][0] = 2; gp.tIdx[2][1] = 2;
    for (int s = 0; s < 3; s++)
        for (int q = 0; q < 2; q++) {
            int t = gp.tIdx[s][q];
            gp.aggOff[s][q] = aggOffA[t];
            gp.cntOff[s][q] = cntOffA[t];
            gp.bias[s][q] = (const float*)d_in[14 + 3 * t];
        }
    int bE = (NE + 127) / 128;
    int bF = (NF + 127) / 128;
    int bA = (NA + 127) / 128;
    gp.blkPrefix[0] = 0;
    gp.blkPrefix[1] = bE;
    gp.blkPrefix[2] = bE + bF;
    gp.blkPrefix[3] = bE + bF + bA;

    int smemBytes = STAGES * 2 * TILEW * 4;      // 110592
    cudaFuncSetAttribute(gemm_kernel,
                         cudaFuncAttributeMaxDynamicSharedMemorySize, smemBytes);

    prep_kernel<<<(5 * 2 * D * D) / 256, 256>>>(pp);

    long long cthr = (cp.prefix[3] + 7) / 8;
    cvt_kernel<<<(int)((cthr + 255) / 256), 256>>>(cp);

    long long nw = (eCum + 1) / 2;               // two edges per warp
    long long thr = nw * 32;
    int sblk = (int)((thr + 255) / 256);
    scatter_kernel<<<sblk, 256>>>(sp);

    gemm_kernel<<<gp.blkPrefix[3], 256, smemBytes>>>(gp);
}

// round 16
// speedup vs baseline: 1.8973x; 1.0073x over previous
#include <cuda_runtime.h>
#include <cuda_fp16.h>
#include <math.h>

#define D 128

// ---------------------------------------------------------------------------
// Scratch (device globals — zero-init at load; kernels restore the all-zero
// invariant every call; g_xH / g_Bh are fully rewritten every call).
// ---------------------------------------------------------------------------
#define MAXROWS 716800          // >= NE+NF+NA+NF+NE = 700000
#define MAXSRC  409600          // >= NA+NE+NF = 400000
__device__ __half   g_aggH[(size_t)MAXROWS * D];  // fp16 segment sums (self-zeroing)
__device__ float    g_cnt[MAXROWS];               // counts (self-zeroing)
__device__ __half   g_xH[(size_t)MAXSRC * D];     // fp16 feature tables [xa;xe;xf]
__device__ __half   g_Bh[5 * 2 * D * D];          // fp16 weights: [t][wl|wr][n][k]

// ---------------------------------------------------------------------------
// prep: convert all 5 wl / wr matrices to fp16. Layout [t][side][n*128+k]
// ---------------------------------------------------------------------------
struct PrepParams { const float* wl[5]; const float* wr[5]; };

__global__ void prep_kernel(PrepParams p) {
    int i = blockIdx.x * blockDim.x + threadIdx.x;      // 0 .. 163839
    int t = i >> 15;
    int r = i & 32767;
    int side = r >> 14;
    int idx = r & 16383;
    float v = (side ? p.wr[t] : p.wl[t])[idx];
    g_Bh[i] = __float2half_rn(v);
}

// ---------------------------------------------------------------------------
// cvt: stream-convert the three feature tables fp32 -> fp16 into g_xH.
// ---------------------------------------------------------------------------
struct CvtParams { const float* src[3]; long long prefix[4]; };  // prefix in floats

__global__ void cvt_kernel(CvtParams p) {
    long long i = (long long)blockIdx.x * blockDim.x + threadIdx.x;
    long long f = i * 8;
    if (f >= p.prefix[3]) return;
    int t = 0;
    while (f >= p.prefix[t + 1]) t++;
    long long loc = f - p.prefix[t];
    const float4* s = (const float4*)(p.src[t] + loc);
    float4 a = s[0], b = s[1];
    __half2 h0 = __floats2half2_rn(a.x, a.y);
    __half2 h1 = __floats2half2_rn(a.z, a.w);
    __half2 h2 = __floats2half2_rn(b.x, b.y);
    __half2 h3 = __floats2half2_rn(b.z, b.w);
    uint4 o;
    o.x = *(unsigned*)&h0; o.y = *(unsigned*)&h1;
    o.z = *(unsigned*)&h2; o.w = *(unsigned*)&h3;
    *(uint4*)(g_xH + p.prefix[t] + loc) = o;
}

// ---------------------------------------------------------------------------
// Mega-scatter: TWO edges per warp (MLP 2), fp16 gathers + fp16x2 RED.
// ---------------------------------------------------------------------------
struct ScatParams {
    size_t srcOff[5];       // source-table base in g_xH (halfs)
    const int* si[5];
    const int* di[5];
    size_t aggOff[5];       // in halfs
    int    cntOff[5];
    long long ePrefix[6];   // cumulative EDGE counts
};

__global__ void scatter_kernel(ScatParams p) {
    long long gt = (long long)blockIdx.x * blockDim.x + threadIdx.x;
    long long w = gt >> 5;
    int c = (int)(gt & 31);
    long long E = p.ePrefix[5];
    long long e0 = w * 2;
    if (e0 >= E) return;
    long long e1 = e0 + 1;
    bool has1 = (e1 < E);

    int t0 = 0;
    while (e0 >= p.ePrefix[t0 + 1]) t0++;
    int i0 = (int)(e0 - p.ePrefix[t0]);
    int s0 = p.si[t0][i0];
    int d0 = p.di[t0][i0];

    int t1 = t0, s1 = 0, d1 = 0;
    if (has1) {
        while (e1 >= p.ePrefix[t1 + 1]) t1++;
        int i1 = (int)(e1 - p.ePrefix[t1]);
        s1 = p.si[t1][i1];
        d1 = p.di[t1][i1];
    }

    // both gathers issued back-to-back (independent chains)
    uint2 v0 = ((const uint2*)(g_xH + p.srcOff[t0] + (size_t)s0 * D))[c];
    uint2 v1 = make_uint2(0, 0);
    if (has1) v1 = ((const uint2*)(g_xH + p.srcOff[t1] + (size_t)s1 * D))[c];

    __half* dst0 = g_aggH + p.aggOff[t0] + (size_t)d0 * D + c * 4;
    asm volatile("red.global.add.noftz.v2.f16x2 [%0], {%1,%2};"
                 :: "l"(dst0), "r"(v0.x), "r"(v0.y) : "memory");
    if (c == 0) atomicAdd(g_cnt + p.cntOff[t0] + d0, 1.0f);

    if (has1) {
        __half* dst1 = g_aggH + p.aggOff[t1] + (size_t)d1 * D + c * 4;
        asm volatile("red.global.add.noftz.v2.f16x2 [%0], {%1,%2};"
                     :: "l"(dst1), "r"(v1.x), "r"(v1.y) : "memory");
        if (c == 0) atomicAdd(g_cnt + p.cntOff[t1] + d1, 1.0f);
    }
}

// ---------------------------------------------------------------------------
// FUSED Mega-GEMM, all-fp16, f32 accum, cp.async 3-stage pipeline that runs
// CONTINUOUSLY across passes: global tiles 0..4*npass-1 (4p..4p+3 = pass p:
// agg,agg,xd,xd). The prefetch window crosses pass boundaries, so pass p's
// epilogue (bias, L2-norm, store, agg rezero) overlaps pass p+1's loads.
// Pass 0 plain store, pass 1 load-add-store (L2-hot, same rows).
// ---------------------------------------------------------------------------
__device__ __forceinline__ void mma_f16(float* c, const unsigned* a,
                                        unsigned b0, unsigned b1) {
    asm volatile(
        "mma.sync.aligned.m16n8k16.row.col.f32.f16.f16.f32 "
        "{%0,%1,%2,%3}, {%4,%5,%6,%7}, {%8,%9}, {%0,%1,%2,%3};"
        : "+f"(c[0]), "+f"(c[1]), "+f"(c[2]), "+f"(c[3])
        : "r"(a[0]), "r"(a[1]), "r"(a[2]), "r"(a[3]), "r"(b0), "r"(b1));
}

struct GemmParams {
    size_t       xdOff[3];       // dst-node features base in g_xH (halfs)
    float*       out[3];
    int          nd[3];
    int          npass[3];
    int          blkPrefix[4];
    const float* bias[3][2];
    size_t       aggOff[3][2];   // in halfs
    int          cntOff[3][2];
    int          tIdx[3][2];
};

#define TILEW (128 * 36)     // words per As or Bs buffer (stride 36 -> 144B)
#define STAGES 3

__global__ __launch_bounds__(256, 2) void gemm_kernel(GemmParams p) {
    extern __shared__ unsigned sm[];   // STAGES * [As | Bs]
    typedef unsigned Row36[36];

    int b = blockIdx.x;
    int seg = (b >= p.blkPrefix[1]) + (b >= p.blkPrefix[2]);
    int rowBase = (b - p.blkPrefix[seg]) * 128;
    int n_dst = p.nd[seg];
    const __half* xdH = g_xH + p.xdOff[seg];
    float* outp = p.out[seg];
    int npass = p.npass[seg];
    int totTiles = npass * 4;

    __shared__ float rowsum[2][128];
    __shared__ float invc_s[2][128];

    int tid = threadIdx.x;
    int wid = tid >> 5, lane = tid & 31;
    int warpM = wid & 3, warpN = wid >> 2;
    int lq = lane & 3;
    int lr = lane >> 2;

    unsigned smBase = (unsigned)__cvta_generic_to_shared(sm);

    // counts for ALL passes: read once, rezero in place
    if (tid < 128) {
        int gr = rowBase + tid;
        for (int q = 0; q < npass; q++) {
            float* cnt = g_cnt + p.cntOff[seg][q];
            float cc = 1.0f;
            if (gr < n_dst) { cc = cnt[gr]; cnt[gr] = 0.0f; }
            invc_s[q][tid] = 1.0f / fmaxf(cc, 1.0f);
        }
    }
    __syncthreads();

    float acc[2][8][4];
#pragma unroll
    for (int mt = 0; mt < 2; mt++)
#pragma unroll
        for (int nt = 0; nt < 8; nt++)
#pragma unroll
            for (int r = 0; r < 4; r++) acc[mt][nt][r] = 0.f;

    // global tile g: pass = g>>2, lk = g&3; lk<2 -> agg@wr, lk>=2 -> xd@wl
    auto issueTile = [&](int g, int buf) {
        int pass = g >> 2;
        int lk = g & 3;
        bool isAgg = (lk < 2);
        const __half* wlH = g_Bh + (size_t)p.tIdx[seg][pass] * 32768;
        const char* aSrc = isAgg
            ? (const char*)(g_aggH + p.aggOff[seg][pass])
            : (const char*)xdH;
        const char* bSrc = isAgg ? (const char*)(wlH + 16384)
                                 : (const char*)wlH;
        int kB = (lk & 1) * 128;
        unsigned aBase = smBase + (unsigned)(buf * 2 * TILEW) * 4u;
        unsigned bBase = aBase + (unsigned)TILEW * 4u;
#pragma unroll
        for (int it = 0; it < 4; it++) {
            int f = it * 256 + tid;       // 0..1023 16B chunks
            int r = f >> 3;
            int c4 = f & 7;
            int gr = rowBase + r;
            unsigned ad = aBase + (unsigned)(r * 36 + c4 * 4) * 4u;
            const char* asrc = aSrc + (size_t)gr * 256 + kB + c4 * 16;
            int sz = (gr < n_dst) ? 16 : 0;     // OOB -> zero-fill
            asm volatile("cp.async.cg.shared.global [%0], [%1], 16, %2;"
                         :: "r"(ad), "l"(asrc), "r"(sz));
            unsigned bd = bBase + (unsigned)(r * 36 + c4 * 4) * 4u;
            const char* bsrc = bSrc + (size_t)r * 256 + kB + c4 * 16;
            asm volatile("cp.async.cg.shared.global [%0], [%1], 16;"
                         :: "r"(bd), "l"(bsrc));
        }
        asm volatile("cp.async.commit_group;" ::: "memory");
    };

    issueTile(0, 0);
    if (totTiles > 1) issueTile(1, 1);

    for (int g = 0; g < totTiles; g++) {
        int buf = g % STAGES;
        if (g < totTiles - 1)
            asm volatile("cp.async.wait_group 1;" ::: "memory");
        else
            asm volatile("cp.async.wait_group 0;" ::: "memory");
        __syncthreads();          // tile g visible; mma on buf's prior tile done
        if (g + 2 < totTiles) issueTile(g + 2, (g + 2) % STAGES);

        Row36* As = (Row36*)(sm + buf * 2 * TILEW);
        Row36* Bs = As + 128;
#pragma unroll
        for (int q = 0; q < 4; q++) {
            int kq = q * 8 + lq;
            unsigned a[2][4];
#pragma unroll
            for (int mt = 0; mt < 2; mt++) {
                int r0 = warpM * 32 + mt * 16 + lr;
                a[mt][0] = As[r0][kq];
                a[mt][1] = As[r0 + 8][kq];
                a[mt][2] = As[r0][kq + 4];
                a[mt][3] = As[r0 + 8][kq + 4];
            }
#pragma unroll
            for (int nt = 0; nt < 8; nt++) {
                int n0 = warpN * 64 + nt * 8 + lr;
                unsigned b0 = Bs[n0][kq];
                unsigned b1 = Bs[n0][kq + 4];
                mma_f16(acc[0][nt], a[0], b0, b1);
                mma_f16(acc[1][nt], a[1], b0, b1);
            }
        }

        int pass = g >> 2;
        int lk = g & 3;

        if (lk == 1) {
            // finished aggSum@wr^T: scale by 1/cnt; xd@wl^T adds on top
#pragma unroll
            for (int mt = 0; mt < 2; mt++) {
                int r0 = warpM * 32 + mt * 16 + lr;
                float s0 = invc_s[pass][r0];
                float s1 = invc_s[pass][r0 + 8];
#pragma unroll
                for (int nt = 0; nt < 8; nt++) {
                    acc[mt][nt][0] *= s0; acc[mt][nt][1] *= s0;
                    acc[mt][nt][2] *= s1; acc[mt][nt][3] *= s1;
                }
            }
        }

        if (lk == 3) {
            // ---- epilogue for this pass (overlaps next pass's cp.asyncs) ----
            __half* aggH = g_aggH + p.aggOff[seg][pass];
            // rezero this pass's agg rows: 128 rows x 256B = 2048 uint4
#pragma unroll
            for (int it = 0; it < 8; it++) {
                int f = it * 256 + tid;
                int r = f >> 4;
                int c = f & 15;
                int gr = rowBase + r;
                if (gr < n_dst)
                    *(uint4*)((char*)(aggH + (size_t)gr * D) + c * 16) =
                        make_uint4(0, 0, 0, 0);
            }

            const float* bias = p.bias[seg][pass];
            float biasv[16];
#pragma unroll
            for (int nt = 0; nt < 8; nt++) {
                float2 bb = *(const float2*)(bias + warpN * 64 + nt * 8 + 2 * lq);
                biasv[2 * nt] = bb.x;
                biasv[2 * nt + 1] = bb.y;
            }

            float ps[2][2] = {{0.f, 0.f}, {0.f, 0.f}};
#pragma unroll
            for (int mt = 0; mt < 2; mt++)
#pragma unroll
                for (int nt = 0; nt < 8; nt++) {
                    acc[mt][nt][0] += biasv[2 * nt];
                    acc[mt][nt][1] += biasv[2 * nt + 1];
                    acc[mt][nt][2] += biasv[2 * nt];
                    acc[mt][nt][3] += biasv[2 * nt + 1];
                    ps[mt][0] += acc[mt][nt][0] * acc[mt][nt][0]
                               + acc[mt][nt][1] * acc[mt][nt][1];
                    ps[mt][1] += acc[mt][nt][2] * acc[mt][nt][2]
                               + acc[mt][nt][3] * acc[mt][nt][3];
                }
#pragma unroll
            for (int mt = 0; mt < 2; mt++)
#pragma unroll
                for (int h = 0; h < 2; h++) {
                    float v = ps[mt][h];
                    v += __shfl_xor_sync(0xffffffffu, v, 1);
                    v += __shfl_xor_sync(0xffffffffu, v, 2);
                    if (lq == 0)
                        rowsum[warpN][warpM * 32 + mt * 16 + h * 8 + lr] = v;
                }
            __syncthreads();

#pragma unroll
            for (int mt = 0; mt < 2; mt++)
#pragma unroll
                for (int h = 0; h < 2; h++) {
                    int rloc = warpM * 32 + mt * 16 + h * 8 + lr;
                    int gr = rowBase + rloc;
                    if (gr >= n_dst) continue;
                    float ss = rowsum[0][rloc] + rowsum[1][rloc];
                    float inv = 1.f / fmaxf(sqrtf(ss), 1e-12f);
#pragma unroll
                    for (int nt = 0; nt < 8; nt++) {
                        float vx = acc[mt][nt][h * 2 + 0] * inv;
                        float vy = acc[mt][nt][h * 2 + 1] * inv;
                        float* pp = outp + (size_t)gr * D + warpN * 64
                                    + nt * 8 + 2 * lq;
                        if (pass == 0) {
                            *(float2*)pp = make_float2(vx, vy);
                        } else {
                            float2 old = *(const float2*)pp;   // L2-hot
                            *(float2*)pp = make_float2(old.x + vx, old.y + vy);
                        }
                    }
                }

            if (g + 1 < totTiles) {
                // reset accumulators for the next pass
#pragma unroll
                for (int mt = 0; mt < 2; mt++)
#pragma unroll
                    for (int nt = 0; nt < 8; nt++)
#pragma unroll
                        for (int r = 0; r < 4; r++) acc[mt][nt][r] = 0.f;
                __syncthreads();   // rowsum reuse ordering for next pass
            }
        }
    }
}

// ---------------------------------------------------------------------------
// Host orchestration — single stream, 4 launches: prep, cvt, mega-scatter,
// fused gemm.
// ---------------------------------------------------------------------------
extern "C" void kernel_launch(void* const* d_in, const int* in_sizes, int n_in,
                              void* d_out, int out_size) {
    const float* xa = (const float*)d_in[0];
    const float* xe = (const float*)d_in[1];
    const float* xf = (const float*)d_in[2];
    int NA = in_sizes[0] / D;
    int NE = in_sizes[1] / D;
    int NF = in_sizes[2] / D;

    float* out = (float*)d_out;
    float* out_a = out;
    float* out_e = out + (size_t)NA * D;
    float* out_f = out + (size_t)(NA + NE) * D;

    // g_xH layout: [xa ; xe ; xf] (halfs)
    size_t offA = 0;
    size_t offE = (size_t)NA * D;
    size_t offF = (size_t)(NA + NE) * D;

    // EDGE_TYPES: (a->e), (a->f), (e->a), (e->f), (f->e)
    size_t srcOff_t[5] = {offA, offA, offE, offE, offF};
    int nd_t[5]        = {NE, NF, NA, NF, NE};

    PrepParams pp;
    ScatParams sp;
    CvtParams cp;

    cp.src[0] = xa; cp.src[1] = xe; cp.src[2] = xf;
    cp.prefix[0] = 0;
    cp.prefix[1] = (long long)NA * D;
    cp.prefix[2] = (long long)(NA + NE) * D;
    cp.prefix[3] = (long long)(NA + NE + NF) * D;

    size_t aggOffA[5];
    int cntOffA[5];
    int rowCum = 0;
    long long eCum = 0;
    sp.ePrefix[0] = 0;
    for (int t = 0; t < 5; t++) {
        pp.wl[t] = (const float*)d_in[13 + 3 * t];
        pp.wr[t] = (const float*)d_in[15 + 3 * t];
        sp.srcOff[t] = srcOff_t[t];
        sp.si[t] = (const int*)d_in[3 + 2 * t];
        sp.di[t] = (const int*)d_in[4 + 2 * t];
        sp.aggOff[t] = (size_t)rowCum * D;
        sp.cntOff[t] = rowCum;
        aggOffA[t] = (size_t)rowCum * D;
        cntOffA[t] = rowCum;
        rowCum += nd_t[t];
        eCum += in_sizes[3 + 2 * t];
        sp.ePrefix[t + 1] = eCum;
    }

    // Fused GEMM segments: entity (2-pass), fact (2-pass), article (1-pass).
    GemmParams gp;
    gp.xdOff[0] = offE;  gp.out[0] = out_e;  gp.nd[0] = NE;  gp.npass[0] = 2;
    gp.tIdx[0][0] = 0; gp.tIdx[0][1] = 4;
    gp.xdOff[1] = offF;  gp.out[1] = out_f;  gp.nd[1] = NF;  gp.npass[1] = 2;
    gp.tIdx[1][0] = 1; gp.tIdx[1][1] = 3;
    gp.xdOff[2] = offA;  gp.out[2] = out_a;  gp.nd[2] = NA;  gp.npass[2] = 1;
    gp.tIdx[2][0] = 2; gp.tIdx[2][1] = 2;
    for (int s = 0; s < 3; s++)
        for (int q = 0; q < 2; q++) {
            int t = gp.tIdx[s][q];
            gp.aggOff[s][q] = aggOffA[t];
            gp.cntOff[s][q] = cntOffA[t];
            gp.bias[s][q] = (const float*)d_in[14 + 3 * t];
        }
    int bE = (NE + 127) / 128;
    int bF = (NF + 127) / 128;
    int bA = (NA + 127) / 128;
    gp.blkPrefix[0] = 0;
    gp.blkPrefix[1] = bE;
    gp.blkPrefix[2] = bE + bF;
    gp.blkPrefix[3] = bE + bF + bA;

    int smemBytes = STAGES * 2 * TILEW * 4;      // 110592
    cudaFuncSetAttribute(gemm_kernel,
                         cudaFuncAttributeMaxDynamicSharedMemorySize, smemBytes);

    prep_kernel<<<(5 * 2 * D * D) / 256, 256>>>(pp);

    long long cthr = (cp.prefix[3] + 7) / 8;
    cvt_kernel<<<(int)((cthr + 255) / 256), 256>>>(cp);

    long long nw = (eCum + 1) / 2;               // two edges per warp
    long long thr = nw * 32;
    int sblk = (int)((thr + 255) / 256);
    scatter_kernel<<<sblk, 256>>>(sp);

    gemm_kernel<<<gp.blkPrefix[3], 256, smemBytes>>>(gp);
}